// round 16
// baseline (speedup 1.0000x reference)
#include <cuda_runtime.h>
#include <cuda_bf16.h>
#include <cstdint>

#define COUNT   8
#define OUT_F   32
#define IN_F    1024
#define MAXB    8192
#define TILE_M  64
#define NT_Y    18          // 18*64 = 1152 capacity/bank; 144 CTAs = 1 wave
#define NTHR    512
#define WROW    1032        // W smem row stride in u16 (2064B, LDSM conflict-free)

// dynamic smem layout (bytes)
#define SM_SIDS   66048     // W [32][1032] u16 occupies [0, 66048)
#define SM_ALPHA  66304
#define SM_BIAS   66432
#define SM_X      66560     // FULL x tile: 64 rows x 2096B (1024 fp16 + 48B pad)
#define XSTRIDE   2096      // 2096/4 % 32 = 12 -> 8-row LDSM sets hit 32 distinct banks
#define SM_RED    SM_X      // reduction aliases x tile post-consume (barrier-ordered)
#define SM_TOTAL  (SM_X + 64 * XSTRIDE)   // 200704 < 227KB opt-in cap

// device scratch (no allocation anywhere)
__device__ __align__(16) unsigned short g_whf[COUNT * OUT_F * IN_F]; // int-valued fp16 [row][k]
__device__ float g_alpha[COUNT * OUT_F];
__device__ int   g_cnt[COUNT];     // invariant: ==0 at kernel_launch entry
__device__ int   g_order[COUNT * MAXB];

__device__ __forceinline__ unsigned packh2(float lo, float hi) {    // low half = lo
    unsigned r; asm("cvt.rn.f16x2.f32 %0, %1, %2;" : "=r"(r) : "f"(hi), "f"(lo)); return r;
}
__device__ __forceinline__ unsigned smem_u32(const void* p) {
    unsigned r;
    asm("{ .reg .u64 t; cvta.to.shared.u64 t, %1; cvt.u32.u64 %0, t; }" : "=r"(r) : "l"(p));
    return r;
}
#define MMA_F16(d, a, b) \
    asm volatile("mma.sync.aligned.m16n8k16.row.col.f32.f16.f16.f32 " \
        "{%0,%1,%2,%3}, {%4,%5,%6,%7}, {%8,%9}, {%0,%1,%2,%3};" \
        : "+f"(d[0]), "+f"(d[1]), "+f"(d[2]), "+f"(d[3]) \
        : "r"(a[0]), "r"(a[1]), "r"(a[2]), "r"(a[3]), "r"(b[0]), "r"(b[1]))
#define LDSM4(r, addr) \
    asm volatile("ldmatrix.sync.aligned.m8n8.x4.shared.b16 {%0,%1,%2,%3}, [%4];" \
        : "=r"(r[0]), "=r"(r[1]), "=r"(r[2]), "=r"(r[3]) : "r"(addr))

// ---------------------------------------------------------------------------
// Kernel 1 (fused): CTAs 0..63 quantize (4 weight rows each, MLP-4 loads) into
// exact integer-valued fp16; CTAs 64..79 run the 8-bucket counting scatter.
// ---------------------------------------------------------------------------
__global__ void __launch_bounds__(256) prep_kernel(
        const float* __restrict__ weight,
        const float* __restrict__ log_alpha,
        const int*   __restrict__ ls_raw,
        int B) {
    int tid = threadIdx.x, bid = blockIdx.x;
    if (bid < 64) {
        int row = bid * 4 + (tid >> 6);
        int lt  = tid & 63;
        float a = expf(log_alpha[row]);
        float rc = 1.0f / a;
        if (lt == 0) g_alpha[row] = a;
        const float* src = weight + (size_t)row * IN_F;
        unsigned short* dst = g_whf + (size_t)row * IN_F;
        float4 v[4];
#pragma unroll
        for (int j = 0; j < 4; j++)
            v[j] = *(const float4*)(src + j * 256 + lt * 4);
#pragma unroll
        for (int j = 0; j < 4; j++) {
            float i0 = rintf(fminf(fmaxf(v[j].x * rc, -128.f), 127.f));
            float i1 = rintf(fminf(fmaxf(v[j].y * rc, -128.f), 127.f));
            float i2 = rintf(fminf(fmaxf(v[j].z * rc, -128.f), 127.f));
            float i3 = rintf(fminf(fmaxf(v[j].w * rc, -128.f), 127.f));
            uint2 pk; pk.x = packh2(i0, i1); pk.y = packh2(i2, i3);  // exact: |int|<=128
            *(uint2*)(dst + j * 256 + lt * 4) = pk;
        }
    } else {
        __shared__ int hist[COUNT], base[COUNT], s_s2;
        if (tid == 0) {                        // int64 iff all odd int32 words zero
            int s2 = 1;
            int lim = (B < 32) ? B : 32;
            for (int i = 0; i < lim; i++)
                if (ls_raw[2 * i + 1] != 0) { s2 = 0; break; }
            s_s2 = s2;
        }
        __syncthreads();
        int s2 = s_s2;
        for (int start = (bid - 64) * 512; start < B; start += 16 * 512) {
            if (tid < COUNT) hist[tid] = 0;
            __syncthreads();
            int bA = start + tid, bB = start + tid + 256;
            int cA = 0, cB = 0, rA = 0, rB = 0;
            bool vA = bA < B, vB = bB < B;
            if (vA) { cA = ls_raw[s2 ? 2 * bA : bA] & 7; rA = atomicAdd(&hist[cA], 1); }
            if (vB) { cB = ls_raw[s2 ? 2 * bB : bB] & 7; rB = atomicAdd(&hist[cB], 1); }
            __syncthreads();
            if (tid < COUNT) base[tid] = atomicAdd(&g_cnt[tid], hist[tid]);
            __syncthreads();
            if (vA) g_order[cA * MAXB + base[cA] + rA] = bA;
            if (vB) g_order[cB * MAXB + base[cB] + rB] = bB;
            __syncthreads();
        }
    }
}

// ---------------------------------------------------------------------------
// Kernel 2: grouped GEMM, phase-separated.
// Phase 1: ALL threads stream their x rows gmem->fp16 smem (full 64x1024 tile,
//          2-batch load ring, nothing blocks the LDG stream). W preload rides
//          in the same shadow. ONE barrier.
// Phase 2: pure-smem compute: warp=(mg,ks); per kc: ldmatrix A (x tile) +
//          2x ldmatrix B (W tile) + 4 MMAs. No gmem, no cvt in the loop.
// Then k-split reduction (aliases x tile) + alpha*acc+bias epilogue.
// CTA (c, y=0) resets g_cnt[c] (single wave: all reads precede it).
// ---------------------------------------------------------------------------
__global__ void __launch_bounds__(NTHR, 1) gemm_kernel(
        const float* __restrict__ x,
        const float* __restrict__ bias,
        float* __restrict__ out) {
    extern __shared__ __align__(16) char smem[];
    unsigned short* wsm = (unsigned short*)smem;
    int*   sids = (int*)(smem + SM_SIDS);
    float* sal  = (float*)(smem + SM_ALPHA);
    float* sbi  = (float*)(smem + SM_BIAS);
    float* red  = (float*)(smem + SM_RED);

    int c = blockIdx.x;
    int n = g_cnt[c];
    int start = blockIdx.y * TILE_M;
    int tid = threadIdx.x, lane = tid & 31, wid = tid >> 5;

    if (start >= n) {
        if (blockIdx.y == 0 && tid == 0) g_cnt[c] = 0;
        return;
    }
    int m = n - start; if (m > TILE_M) m = TILE_M;

    if (tid < TILE_M) {
        int p = start + tid; if (p >= n) p = n - 1;   // clamp; dup rows masked at store
        sids[tid] = g_order[c * MAXB + p];
    }
    if (tid < 32) { sal[tid] = g_alpha[c * OUT_F + tid]; sbi[tid] = bias[c * OUT_F + tid]; }
    __syncthreads();     // sids needed for producer addresses

    // ================= Phase 1: stream full x tile to smem ==================
    {
        int prow = tid >> 3, pseg = tid & 7;
        const float* gx = x + (size_t)sids[prow] * IN_F + pseg * 4;
        char* xrow = smem + SM_X + prow * XSTRIDE + pseg * 8;

        // batch b covers cols (b*8+jj)*32 + pseg*4 ; 4 batches of 8 LDG.128
        float4 Lb[2][8];
#pragma unroll
        for (int jj = 0; jj < 8; jj++) Lb[0][jj] = *(const float4*)(gx + jj * 32);
#pragma unroll
        for (int jj = 0; jj < 8; jj++) Lb[1][jj] = *(const float4*)(gx + 256 + jj * 32);

        // W preload LDGs (66KB/CTA) issue in the shadow of the x stream
        const unsigned short* wsrc = g_whf + (size_t)c * OUT_F * IN_F;
        uint4 wv[8];
#pragma unroll
        for (int i = 0; i < 8; i++) {
            int idx = tid + i * NTHR;
            wv[i] = *(const uint4*)(wsrc + (idx >> 7) * IN_F + (idx & 127) * 8);
        }

#pragma unroll
        for (int w = 0; w < 4; w++) {
            char* dst = xrow + w * 512;      // batch stride: 8*32 cols * 2B
#pragma unroll
            for (int jj = 0; jj < 8; jj++) {
                float4 v = Lb[w & 1][jj];
                uint2 pk; pk.x = packh2(v.x, v.y); pk.y = packh2(v.z, v.w);
                *(uint2*)(dst + jj * 64) = pk;
            }
            if (w + 2 < 4) {
                const float* gsrc = gx + (w + 2) * 256;
#pragma unroll
                for (int jj = 0; jj < 8; jj++)
                    Lb[w & 1][jj] = *(const float4*)(gsrc + jj * 32);
            }
        }
#pragma unroll
        for (int i = 0; i < 8; i++) {
            int idx = tid + i * NTHR;
            *(uint4*)(wsm + (idx >> 7) * WROW + (idx & 127) * 8) = wv[i];
        }
    }
    __syncthreads();     // full x tile + W visible

    // ================= Phase 2: pure-smem tensor compute ====================
    int mg = wid & 3;                  // rows mg*16 .. mg*16+15
    int ks = wid >> 2;                 // k-quarter: kc = ks*16 .. ks*16+15
    int g = lane >> 2, t = lane & 3;
    int r0 = mg * 16 + g, r1 = r0 + 8;

    unsigned xb0 = smem_u32(smem + SM_X);
    int arow = mg * 16 + (lane & 7) + ((lane >> 3) & 1) * 8;
    unsigned xa = xb0 + (unsigned)(arow * XSTRIDE + ((lane >> 4) & 1) * 16 + ks * 512);

    unsigned wb = smem_u32(wsm);
    int q8 = lane & 7, seg2 = lane >> 3;
    unsigned ba0 = wb + (unsigned)(((seg2 & 2) * 4 + q8) * (WROW * 2) + (seg2 & 1) * 16 + ks * 512);
    unsigned ba1 = ba0 + 16u * (WROW * 2);   // n blocks 2,3

    float acc[4][4];
#pragma unroll
    for (int nb = 0; nb < 4; nb++)
#pragma unroll
        for (int i = 0; i < 4; i++) acc[nb][i] = 0.f;

#pragma unroll
    for (int kcl = 0; kcl < 16; kcl++) {
        unsigned a[4], b0[4], b1[4];
        LDSM4(a,  xa  + kcl * 32);
        LDSM4(b0, ba0 + kcl * 32);
        LDSM4(b1, ba1 + kcl * 32);
        MMA_F16(acc[0], a, (b0 + 0));
        MMA_F16(acc[1], a, (b0 + 2));
        MMA_F16(acc[2], a, (b1 + 0));
        MMA_F16(acc[3], a, (b1 + 2));
    }

    __syncthreads();   // x tile consumed; safe to alias as reduction buffer
    // k-split reduction: ks>0 warps park partials; ks==0 combines
    if (ks > 0) {
        float* dst = red + ((ks - 1) * 4 + mg) * 512;
#pragma unroll
        for (int nb = 0; nb < 4; nb++)
#pragma unroll
            for (int i = 0; i < 4; i++)
                dst[(nb * 4 + i) * 32 + lane] = acc[nb][i];
    }
    __syncthreads();
    if (ks == 0) {
#pragma unroll
        for (int j = 0; j < 3; j++) {
            const float* srcp = red + (j * 4 + mg) * 512;
#pragma unroll
            for (int nb = 0; nb < 4; nb++)
#pragma unroll
                for (int i = 0; i < 4; i++)
                    acc[nb][i] += srcp[(nb * 4 + i) * 32 + lane];
        }
        // epilogue: out = alpha_col * acc + bias_col
        bool v0 = (mg * 16 + g) < m, v1 = (mg * 16 + g + 8) < m;
        float* d0 = out + (size_t)sids[r0] * OUT_F;
        float* d1 = out + (size_t)sids[r1] * OUT_F;
#pragma unroll
        for (int nb = 0; nb < 4; nb++) {
            int cc = nb * 8 + 2 * t;
            float A0 = sal[cc], A1 = sal[cc + 1], B0 = sbi[cc], B1 = sbi[cc + 1];
            if (v0) *(float2*)(d0 + cc) = make_float2(A0 * acc[nb][0] + B0, A1 * acc[nb][1] + B1);
            if (v1) *(float2*)(d1 + cc) = make_float2(A0 * acc[nb][2] + B0, A1 * acc[nb][3] + B1);
        }
    }

    // reset bucket counter for next replay (single wave: all g_cnt reads done long ago)
    if (blockIdx.y == 0 && tid == 0) {
        __threadfence();
        g_cnt[c] = 0;
    }
}

// ---------------------------------------------------------------------------
// Inputs (metadata order): x f32[B,1024], ls_indices int[B] (32/64-bit,
// runtime-detected), weight f32[256,1024], bias f32[256], log_alpha_w f32[256].
// Output f32[B,32].
// ---------------------------------------------------------------------------
extern "C" void kernel_launch(void* const* d_in, const int* in_sizes, int n_in,
                              void* d_out, int out_size) {
    const float* x         = (const float*)d_in[0];
    const int*   ls_raw    = (const int*)d_in[1];
    const float* weight    = (const float*)d_in[2];
    const float* bias      = (const float*)d_in[3];
    const float* log_alpha = (const float*)d_in[4];
    float*       out       = (float*)d_out;
    int B = in_sizes[0] / IN_F;

    static int inited = 0;
    if (!inited) {
        cudaFuncSetAttribute(gemm_kernel, cudaFuncAttributeMaxDynamicSharedMemorySize, SM_TOTAL);
        inited = 1;
    }
    prep_kernel<<<80, 256>>>(weight, log_alpha, ls_raw, B);
    dim3 grid(COUNT, NT_Y);
    gemm_kernel<<<grid, NTHR, SM_TOTAL>>>(x, bias, out);
}